// round 12
// baseline (speedup 1.0000x reference)
#include <cuda_runtime.h>
#include <cuda_fp16.h>
#include <math.h>

#define B_    64
#define TIN   256
#define V_    64
#define H_    1024
#define TOUT  32
#define NCTA  128
#define NTHR  512   // 16 warps: m = w&3 (batch tile), kseg = w>>2 (K quarter = epilogue nt)

__device__ __align__(16) __half g_W0f[4456448];
__device__ __align__(16) __half g_W1f[8388608];
__device__ __align__(16) __half g_Wff[65536];
__device__ __align__(16) __half g_XF [1048576];
__device__ __align__(16) __half g_H0F[131072];
__device__ __align__(16) __half g_H1F[131072];
__device__ __align__(16) __half g_INPF[4096];

// two-level barrier state: 8 group counters on separate 256B lines + root + gen
__device__ __align__(256) unsigned g_bar_grp[8 * 64];   // use [g*64]
__device__ unsigned g_bar_root = 0;
__device__ unsigned g_bar_gen  = 0;

__device__ __forceinline__ void mma16816(float* d, const uint4& a,
                                         unsigned b0, unsigned b1) {
    asm volatile(
        "mma.sync.aligned.m16n8k16.row.col.f32.f16.f16.f32 "
        "{%0,%1,%2,%3}, {%4,%5,%6,%7}, {%8,%9}, {%0,%1,%2,%3};\n"
        : "+f"(d[0]), "+f"(d[1]), "+f"(d[2]), "+f"(d[3])
        : "r"(a.x), "r"(a.y), "r"(a.z), "r"(a.w), "r"(b0), "r"(b1));
}

// fast activations: MUFU-based (rel err ~1e-6, far below fp16 noise)
__device__ __forceinline__ float sigm(float x) {
    return __fdividef(1.0f, 1.0f + __expf(-x));
}
__device__ __forceinline__ float tanh_f(float x) {
    return __fdividef(2.0f, 1.0f + __expf(-2.0f * x)) - 1.0f;
}

// hierarchical grid barrier: 16-way group atomics -> 8-way root -> gen flip
__device__ __forceinline__ void grid_sync(int ct) {
    __syncthreads();
    if (threadIdx.x == 0) {
        unsigned gen;
        asm volatile("ld.acquire.gpu.u32 %0, [%1];" : "=r"(gen) : "l"(&g_bar_gen) : "memory");
        __threadfence();
        const int g = ct >> 4;
        if (atomicAdd(&g_bar_grp[g * 64], 1u) == 15u) {
            g_bar_grp[g * 64] = 0u;
            unsigned r;
            asm volatile("atom.add.release.gpu.u32 %0, [%1], 1;"
                         : "=r"(r) : "l"(&g_bar_root) : "memory");
            if (r == 7u) {
                g_bar_root = 0u;
                asm volatile("st.release.gpu.u32 [%0], %1;"
                             :: "l"(&g_bar_gen), "r"(gen + 1u) : "memory");
            }
        }
        unsigned cur;
        do {
            asm volatile("ld.acquire.gpu.u32 %0, [%1];" : "=r"(cur) : "l"(&g_bar_gen) : "memory");
        } while (cur == gen);
        __threadfence();
    }
    __syncthreads();
}

// ---- single merged prep kernel (fragment-order layouts verified R2-R10) ----
#define PW0 4456448
#define PW1 (PW0 + 8388608)
#define PWF (PW1 + 65536)
#define PX  (PWF + 1048576)
__global__ void prep_all(const float* __restrict__ x,  const float* __restrict__ W0,
                         const float* __restrict__ W1, const float* __restrict__ Wf) {
    for (int f = blockIdx.x * blockDim.x + threadIdx.x; f < PX; f += gridDim.x * blockDim.x) {
        if (f < PW0) {
            const int K = 1088, nchunk = 68;
            int e = f & 1, q = (f >> 1) & 3, l = (f >> 3) & 31, ng = (f >> 8) & 1;
            int rest = f >> 9;
            int c = rest % nchunk, ct = rest / nchunk;
            int n = (ng << 4) + ((q >> 1) << 3) + (l >> 2);
            int k = (c << 4) + ((q & 1) << 3) + ((l & 3) << 1) + e;
            int j = (ct << 3) + (n >> 2);
            g_W0f[f] = __float2half(W0[(size_t)((n & 3) * 1024 + j) * K + k]);
        } else if (f < PW1) {
            int f2 = f - PW0;
            const int K = 2048;
            int e = f2 & 1, q = (f2 >> 1) & 3, l = (f2 >> 3) & 31, ng = (f2 >> 8) & 1;
            int rest = f2 >> 9;
            int c = rest & 127, ct = rest >> 7;
            int n = (ng << 4) + ((q >> 1) << 3) + (l >> 2);
            int k = (c << 4) + ((q & 1) << 3) + ((l & 3) << 1) + e;
            int j = (ct << 3) + (n >> 2);
            g_W1f[f2] = __float2half(W1[(size_t)((n & 3) * 1024 + j) * K + k]);
        } else if (f < PWF) {
            int f3 = f - PW1;
            int e = f3 & 1, q = (f3 >> 1) & 3, l = (f3 >> 3) & 31;
            int rest = f3 >> 8;
            int c = rest & 63, vg = rest >> 6;
            int v = (vg << 4) + ((q >> 1) << 3) + (l >> 2);
            int j = (c << 4) + ((q & 1) << 3) + ((l & 3) << 1) + e;
            g_Wff[f3] = __float2half(Wf[(size_t)v * 1024 + j]);
        } else {
            int f4 = f - PWF;
            int e = f4 & 1, q = (f4 >> 1) & 3, l = (f4 >> 3) & 31;
            int rest = f4 >> 8;
            int c = rest & 3, m = (rest >> 2) & 3, t = rest >> 4;
            int b = (m << 4) + ((q & 1) << 3) + (l >> 2);
            int v = (c << 4) + ((q >> 1) << 3) + ((l & 3) << 1) + e;
            g_XF[f4] = __float2half(x[(size_t)(b * TIN + t) * V_ + v]);
        }
    }
}

// ---- GEMM over chunk range of concatenated A0|A1 ----
__device__ __forceinline__ void gemm_range(
    const __half* __restrict__ Wb,
    const __half* __restrict__ A0, int n0,
    const __half* __restrict__ A1,
    int start, int end, float acc[4][4], int lane)
{
    int e0 = min(end, n0);
    {
        const __half* a  = A0 + (size_t)start * 256 + lane * 8;
        const __half* wl = Wb + (size_t)start * 512 + lane * 8;
#pragma unroll 8
        for (int c = start; c < e0; ++c) {
            uint4 av = __ldcg((const uint4*)a);
            uint4 w0 = __ldg((const uint4*)wl);
            uint4 w1 = __ldg((const uint4*)(wl + 256));
            mma16816(acc[0], av, w0.x, w0.y);
            mma16816(acc[1], av, w0.z, w0.w);
            mma16816(acc[2], av, w1.x, w1.y);
            mma16816(acc[3], av, w1.z, w1.w);
            a += 256; wl += 512;
        }
    }
    int s1 = max(start, n0);
    {
        const __half* a  = A1 + (size_t)(s1 - n0) * 256 + lane * 8;
        const __half* wl = Wb + (size_t)s1 * 512 + lane * 8;
#pragma unroll 8
        for (int c = s1; c < end; ++c) {
            uint4 av = __ldcg((const uint4*)a);
            uint4 w0 = __ldg((const uint4*)wl);
            uint4 w1 = __ldg((const uint4*)(wl + 256));
            mma16816(acc[0], av, w0.x, w0.y);
            mma16816(acc[1], av, w0.z, w0.w);
            mma16816(acc[2], av, w1.x, w1.y);
            mma16816(acc[3], av, w1.z, w1.w);
            a += 256; wl += 512;
        }
    }
}

// ---- one LSTM cell phase: K split x4 across kseg; each warp stores only the
//      3 partials it does NOT consume (24KB smem); epilogue parallel across
//      all 16 warps: warp (m,kseg) owns output set (m, nt=kseg). ----
__device__ __forceinline__ void cell_phase(
    const __half* __restrict__ Wb,
    const __half* __restrict__ A0, int n0,
    const __half* __restrict__ A1, int n1,
    const float*  __restrict__ bias,
    float& cr, __half* __restrict__ hout,
    float* __restrict__ red,
    int ct, int kseg, int m, int lane)
{
    float acc[4][4];
#pragma unroll
    for (int i = 0; i < 4; ++i)
#pragma unroll
        for (int k = 0; k < 4; ++k) acc[i][k] = 0.0f;

    const int nc  = n0 + n1;
    const int len = nc >> 2;                    // nc in {4,68,128}
    gemm_range(Wb, A0, n0, A1, kseg * len, kseg * len + len, acc, lane);

    __syncthreads();   // guard smem region reuse
    // store acc[i] for i != kseg: red[(kseg*4+m)*384 + ii*128 + k*32 + lane]
    {
        float* dst = red + (size_t)(kseg * 4 + m) * 384 + lane;
        int ii = 0;
#pragma unroll
        for (int i = 0; i < 4; ++i) {
            if (i != kseg) {
#pragma unroll
                for (int k = 0; k < 4; ++k) dst[(ii * 4 + k) * 32] = acc[i][k];
                ++ii;
            }
        }
    }
    __syncthreads();

    // epilogue: this warp owns nt = kseg; own partial stays in registers
    const int nt = kseg;
    float d[4];
#pragma unroll
    for (int k = 0; k < 4; ++k) d[k] = acc[nt][k];
#pragma unroll
    for (int ks = 0; ks < 4; ++ks) {
        if (ks != nt) {
            const int ii = (nt < ks) ? nt : nt - 1;
            const float* src = red + (size_t)(ks * 4 + m) * 384 + (ii * 4) * 32 + lane;
#pragma unroll
            for (int k = 0; k < 4; ++k) d[k] += src[k * 32];
        }
    }

    const bool hi = (lane & 1);
    int j  = ct * 8 + 2 * nt + ((lane & 3) >> 1);
    int g0 = (lane & 1) * 2;
    float bv0 = __ldg(bias + g0 * 1024 + j);
    float bv1 = __ldg(bias + (g0 + 1) * 1024 + j);
    float d0 = d[0] + bv0, d1 = d[1] + bv1, d2 = d[2] + bv0, d3 = d[3] + bv1;

    float sA = hi ? d0 : d2;
    float sB = hi ? d1 : d3;
    float rA = __shfl_xor_sync(0xffffffffu, sA, 1);
    float rB = __shfl_xor_sync(0xffffffffu, sB, 1);
    float gi = hi ? rA : d0;
    float gf = hi ? rB : d1;
    float gc = hi ? d2 : rA;
    float go = hi ? d3 : rB;

    float cn = sigm(gf) * cr + sigm(gi) * tanh_f(gc);
    cr = cn;
    float hv = sigm(go) * tanh_f(cn);

    int b = m * 16 + (lane >> 2) + (hi ? 8 : 0);
    int ldst = ((b & 7) << 2) + ((j & 7) >> 1);
    int qq = (hi ? 1 : 0) + ((j & 8) ? 2 : 0);
    hout[(size_t)((b >> 4) * 64 + (j >> 4)) * 256 + ldst * 8 + qq * 2 + (j & 1)] =
        __float2half(hv);
}

// ---- main persistent kernel: skewed L0/L1 pipeline, 1 sync per encoder phase ----
__global__ void __launch_bounds__(NTHR, 1)
rnn_main_kernel(const float* __restrict__ b0, const float* __restrict__ b1,
                const float* __restrict__ bf, float* __restrict__ out)
{
    const int ct   = blockIdx.x;
    const int tid  = threadIdx.x;
    const int w    = tid >> 5;
    const int lane = tid & 31;
    const int m    = w & 3;
    const int kseg = w >> 2;

    float c0r = 0.f, c1r = 0.f;

    const __half* Wb0 = g_W0f + (size_t)ct * 68 * 512;
    const __half* Wb1 = g_W1f + (size_t)ct * 128 * 512;

    __shared__ float red[6144];   // 24 KB

    // h0(t) in g_H0F buffer (t&1); h1(t) in g_H1F (t&1).
    for (int p = 0; p <= 256; ++p) {
        if (p < 256) {
            const __half* a0    = g_XF + (size_t)(p * 4 + m) * 1024;
            const __half* h0old = g_H0F + (size_t)((((p - 1) & 1)) * 4 + m) * 16384;
            __half* h0out = g_H0F + (size_t)(p & 1) * 65536;
            cell_phase(Wb0, a0, 4, h0old, p ? 64 : 0, b0, c0r, h0out,
                       red, ct, kseg, m, lane);
        }
        if (p >= 1) {
            const int s1 = p - 1;
            const __half* h0new = g_H0F + (size_t)((s1 & 1) * 4 + m) * 16384;
            const __half* h1old = g_H1F + (size_t)((((s1 - 1) & 1)) * 4 + m) * 16384;
            __half* h1out = g_H1F + (size_t)(s1 & 1) * 65536;
            cell_phase(Wb1, h0new, 64, h1old, s1 ? 64 : 0, b1, c1r, h1out,
                       red, ct, kseg, m, lane);
        }
        grid_sync(ct);
    }

    // Decoder: L0 | sync | L1 | sync | proj | sync
    for (int s = 256; s < 288; ++s) {
        const __half* a0 = (s == 256) ? g_XF + (size_t)(255 * 4 + m) * 1024
                                      : g_INPF + (size_t)m * 1024;
        cell_phase(Wb0, a0, 4,
                   g_H0F + (size_t)(((s - 1) & 1) * 4 + m) * 16384, 64, b0, c0r,
                   g_H0F + (size_t)(s & 1) * 65536, red, ct, kseg, m, lane);
        grid_sync(ct);
        cell_phase(Wb1, g_H0F + (size_t)((s & 1) * 4 + m) * 16384, 64,
                   g_H1F + (size_t)(((s - 1) & 1) * 4 + m) * 16384, 64, b1, c1r,
                   g_H1F + (size_t)(s & 1) * 65536, red, ct, kseg, m, lane);
        grid_sync(ct);

        float pacc[8];
        if (ct < 16 && w < 8) {
            const int mm = ct & 3, vg = ct >> 2;
            const __half* A  = g_H1F + (size_t)((s & 1) * 4 + mm) * 16384
                               + (size_t)(w * 8) * 256 + lane * 8;
            const __half* Wp = g_Wff + (size_t)(vg * 64 + w * 8) * 256 + lane * 8;
#pragma unroll
            for (int k = 0; k < 8; ++k) pacc[k] = 0.0f;
#pragma unroll
            for (int cc = 0; cc < 8; ++cc) {
                uint4 av = __ldcg((const uint4*)(A  + (size_t)cc * 256));
                uint4 wv = __ldg ((const uint4*)(Wp + (size_t)cc * 256));
                mma16816(pacc + 0, av, wv.x, wv.y);
                mma16816(pacc + 4, av, wv.z, wv.w);
            }
            if (w > 0) {
                float* dst = red + (size_t)(w - 1) * 256 + lane;
#pragma unroll
                for (int k = 0; k < 8; ++k) dst[k * 32] = pacc[k];
            }
        }
        __syncthreads();
        if (ct < 16 && w == 0) {
            float fsum[8];
#pragma unroll
            for (int k = 0; k < 8; ++k) fsum[k] = pacc[k];
#pragma unroll
            for (int ww = 1; ww < 8; ++ww) {
                const float* src = red + (size_t)(ww - 1) * 256 + lane;
#pragma unroll
                for (int k = 0; k < 8; ++k) fsum[k] += src[k * 32];
            }
            const int mm = ct & 3, vg = ct >> 2;
            const int tdec = s - TIN;
#pragma unroll
            for (int nt = 0; nt < 2; ++nt)
#pragma unroll
                for (int rr = 0; rr < 2; ++rr)
#pragma unroll
                    for (int e2 = 0; e2 < 2; ++e2) {
                        int b = mm * 16 + (lane >> 2) + rr * 8;
                        int v = vg * 16 + nt * 8 + ((lane & 3) << 1) + e2;
                        float val = fsum[nt * 4 + rr * 2 + e2] + __ldg(bf + v);
                        out[(size_t)(b * TOUT + tdec) * V_ + v] = val;
                        g_INPF[(size_t)((b >> 4) * 4 + (v >> 4)) * 256
                               + (((b & 7) << 2) + ((v & 7) >> 1)) * 8
                               + (rr + ((v & 8) ? 2 : 0)) * 2 + (v & 1)] =
                            __float2half(val);
                    }
        }
        grid_sync(ct);
    }
}

extern "C" void kernel_launch(void* const* d_in, const int* in_sizes, int n_in,
                              void* d_out, int out_size) {
    const float* x  = (const float*)d_in[0];
    const float* W0 = (const float*)d_in[1];
    const float* b0 = (const float*)d_in[2];
    const float* W1 = (const float*)d_in[3];
    const float* b1 = (const float*)d_in[4];
    const float* Wf = (const float*)d_in[5];
    const float* bf = (const float*)d_in[6];
    float* out = (float*)d_out;

    prep_all<<<8192, 256>>>(x, W0, W1, Wf);
    rnn_main_kernel<<<NCTA, NTHR>>>(b0, b1, bf, out);
}

// round 13
// speedup vs baseline: 1.1170x; 1.1170x over previous
#include <cuda_runtime.h>
#include <cuda_fp16.h>
#include <math.h>

#define B_    64
#define TIN   256
#define V_    64
#define H_    1024
#define TOUT  32
#define NCTA  128
#define NTHR  512   // 16 warps: m = w&3 (batch tile), kseg = w>>2 (K quarter = epilogue nt)

__device__ __align__(16) __half g_W0f[4456448];
__device__ __align__(16) __half g_W1f[8388608];
__device__ __align__(16) __half g_Wff[65536];
__device__ __align__(16) __half g_XF [1048576];
__device__ __align__(16) __half g_H0F[131072];
__device__ __align__(16) __half g_H1F[131072];
__device__ __align__(16) __half g_INPF[4096];

__device__ unsigned g_bar_count = 0;
__device__ unsigned g_bar_gen   = 0;

__device__ __forceinline__ void mma16816(float* d, const uint4& a,
                                         unsigned b0, unsigned b1) {
    asm volatile(
        "mma.sync.aligned.m16n8k16.row.col.f32.f16.f16.f32 "
        "{%0,%1,%2,%3}, {%4,%5,%6,%7}, {%8,%9}, {%0,%1,%2,%3};\n"
        : "+f"(d[0]), "+f"(d[1]), "+f"(d[2]), "+f"(d[3])
        : "r"(a.x), "r"(a.y), "r"(a.z), "r"(a.w), "r"(b0), "r"(b1));
}

// fast activations: MUFU-based (rel err ~1e-6, far below fp16 noise)
__device__ __forceinline__ float sigm(float x) {
    return __fdividef(1.0f, 1.0f + __expf(-x));
}
__device__ __forceinline__ float tanh_f(float x) {
    return __fdividef(2.0f, 1.0f + __expf(-2.0f * x)) - 1.0f;
}

// flat grid barrier; generation tracked locally by caller (no entry load)
__device__ __forceinline__ void grid_sync(unsigned gen) {
    __syncthreads();
    if (threadIdx.x == 0) {
        __threadfence();
        unsigned t = atomicAdd(&g_bar_count, 1u);
        if (t == gridDim.x - 1) {
            g_bar_count = 0;
            asm volatile("st.release.gpu.u32 [%0], %1;"
                         :: "l"(&g_bar_gen), "r"(gen + 1u) : "memory");
        } else {
            unsigned cur;
            do {
                asm volatile("ld.acquire.gpu.u32 %0, [%1];"
                             : "=r"(cur) : "l"(&g_bar_gen) : "memory");
            } while ((int)(cur - (gen + 1u)) < 0);
        }
        __threadfence();
    }
    __syncthreads();
}

// ---- single merged prep kernel (fragment-order layouts verified R2-R12) ----
#define PW0 4456448
#define PW1 (PW0 + 8388608)
#define PWF (PW1 + 65536)
#define PX  (PWF + 1048576)
__global__ void prep_all(const float* __restrict__ x,  const float* __restrict__ W0,
                         const float* __restrict__ W1, const float* __restrict__ Wf) {
    for (int f = blockIdx.x * blockDim.x + threadIdx.x; f < PX; f += gridDim.x * blockDim.x) {
        if (f < PW0) {
            const int K = 1088, nchunk = 68;
            int e = f & 1, q = (f >> 1) & 3, l = (f >> 3) & 31, ng = (f >> 8) & 1;
            int rest = f >> 9;
            int c = rest % nchunk, ct = rest / nchunk;
            int n = (ng << 4) + ((q >> 1) << 3) + (l >> 2);
            int k = (c << 4) + ((q & 1) << 3) + ((l & 3) << 1) + e;
            int j = (ct << 3) + (n >> 2);
            g_W0f[f] = __float2half(W0[(size_t)((n & 3) * 1024 + j) * K + k]);
        } else if (f < PW1) {
            int f2 = f - PW0;
            const int K = 2048;
            int e = f2 & 1, q = (f2 >> 1) & 3, l = (f2 >> 3) & 31, ng = (f2 >> 8) & 1;
            int rest = f2 >> 9;
            int c = rest & 127, ct = rest >> 7;
            int n = (ng << 4) + ((q >> 1) << 3) + (l >> 2);
            int k = (c << 4) + ((q & 1) << 3) + ((l & 3) << 1) + e;
            int j = (ct << 3) + (n >> 2);
            g_W1f[f2] = __float2half(W1[(size_t)((n & 3) * 1024 + j) * K + k]);
        } else if (f < PWF) {
            int f3 = f - PW1;
            int e = f3 & 1, q = (f3 >> 1) & 3, l = (f3 >> 3) & 31;
            int rest = f3 >> 8;
            int c = rest & 63, vg = rest >> 6;
            int v = (vg << 4) + ((q >> 1) << 3) + (l >> 2);
            int j = (c << 4) + ((q & 1) << 3) + ((l & 3) << 1) + e;
            g_Wff[f3] = __float2half(Wf[(size_t)v * 1024 + j]);
        } else {
            int f4 = f - PWF;
            int e = f4 & 1, q = (f4 >> 1) & 3, l = (f4 >> 3) & 31;
            int rest = f4 >> 8;
            int c = rest & 3, m = (rest >> 2) & 3, t = rest >> 4;
            int b = (m << 4) + ((q & 1) << 3) + (l >> 2);
            int v = (c << 4) + ((q >> 1) << 3) + ((l & 3) << 1) + e;
            g_XF[f4] = __float2half(x[(size_t)(b * TIN + t) * V_ + v]);
        }
    }
}

// ---- GEMM over chunk range of concatenated A0|A1 ----
__device__ __forceinline__ void gemm_range(
    const __half* __restrict__ Wb,
    const __half* __restrict__ A0, int n0,
    const __half* __restrict__ A1,
    int start, int end, float acc[4][4], int lane)
{
    int e0 = min(end, n0);
    {
        const __half* a  = A0 + (size_t)start * 256 + lane * 8;
        const __half* wl = Wb + (size_t)start * 512 + lane * 8;
#pragma unroll 8
        for (int c = start; c < e0; ++c) {
            uint4 av = __ldcg((const uint4*)a);
            uint4 w0 = __ldg((const uint4*)wl);
            uint4 w1 = __ldg((const uint4*)(wl + 256));
            mma16816(acc[0], av, w0.x, w0.y);
            mma16816(acc[1], av, w0.z, w0.w);
            mma16816(acc[2], av, w1.x, w1.y);
            mma16816(acc[3], av, w1.z, w1.w);
            a += 256; wl += 512;
        }
    }
    int s1 = max(start, n0);
    {
        const __half* a  = A1 + (size_t)(s1 - n0) * 256 + lane * 8;
        const __half* wl = Wb + (size_t)s1 * 512 + lane * 8;
#pragma unroll 8
        for (int c = s1; c < end; ++c) {
            uint4 av = __ldcg((const uint4*)a);
            uint4 w0 = __ldg((const uint4*)wl);
            uint4 w1 = __ldg((const uint4*)(wl + 256));
            mma16816(acc[0], av, w0.x, w0.y);
            mma16816(acc[1], av, w0.z, w0.w);
            mma16816(acc[2], av, w1.x, w1.y);
            mma16816(acc[3], av, w1.z, w1.w);
            a += 256; wl += 512;
        }
    }
}

// ---- one LSTM cell phase: K split x4 across kseg; each warp stores only the
//      3 partials it does NOT consume (24KB smem); epilogue parallel across
//      all 16 warps: warp (m,kseg) owns output set (m, nt=kseg). ----
__device__ __forceinline__ void cell_phase(
    const __half* __restrict__ Wb,
    const __half* __restrict__ A0, int n0,
    const __half* __restrict__ A1, int n1,
    const float*  __restrict__ bias,
    float& cr, __half* __restrict__ hout,
    float* __restrict__ red,
    int ct, int kseg, int m, int lane)
{
    float acc[4][4];
#pragma unroll
    for (int i = 0; i < 4; ++i)
#pragma unroll
        for (int k = 0; k < 4; ++k) acc[i][k] = 0.0f;

    const int nc  = n0 + n1;
    const int len = nc >> 2;                    // nc in {4,68,128}
    gemm_range(Wb, A0, n0, A1, kseg * len, kseg * len + len, acc, lane);

    __syncthreads();   // guard smem region reuse
    // store acc[i] for i != kseg: red[(kseg*4+m)*384 + ii*128 + k*32 + lane]
    {
        float* dst = red + (size_t)(kseg * 4 + m) * 384 + lane;
        int ii = 0;
#pragma unroll
        for (int i = 0; i < 4; ++i) {
            if (i != kseg) {
#pragma unroll
                for (int k = 0; k < 4; ++k) dst[(ii * 4 + k) * 32] = acc[i][k];
                ++ii;
            }
        }
    }
    __syncthreads();

    // epilogue: this warp owns nt = kseg; own partial stays in registers
    const int nt = kseg;
    float d[4];
#pragma unroll
    for (int k = 0; k < 4; ++k) d[k] = acc[nt][k];
#pragma unroll
    for (int ks = 0; ks < 4; ++ks) {
        if (ks != nt) {
            const int ii = (nt < ks) ? nt : nt - 1;
            const float* src = red + (size_t)(ks * 4 + m) * 384 + (ii * 4) * 32 + lane;
#pragma unroll
            for (int k = 0; k < 4; ++k) d[k] += src[k * 32];
        }
    }

    const bool hi = (lane & 1);
    int j  = ct * 8 + 2 * nt + ((lane & 3) >> 1);
    int g0 = (lane & 1) * 2;
    float bv0 = __ldg(bias + g0 * 1024 + j);
    float bv1 = __ldg(bias + (g0 + 1) * 1024 + j);
    float d0 = d[0] + bv0, d1 = d[1] + bv1, d2 = d[2] + bv0, d3 = d[3] + bv1;

    float sA = hi ? d0 : d2;
    float sB = hi ? d1 : d3;
    float rA = __shfl_xor_sync(0xffffffffu, sA, 1);
    float rB = __shfl_xor_sync(0xffffffffu, sB, 1);
    float gi = hi ? rA : d0;
    float gf = hi ? rB : d1;
    float gc = hi ? d2 : rA;
    float go = hi ? d3 : rB;

    float cn = sigm(gf) * cr + sigm(gi) * tanh_f(gc);
    cr = cn;
    float hv = sigm(go) * tanh_f(cn);

    int b = m * 16 + (lane >> 2) + (hi ? 8 : 0);
    int ldst = ((b & 7) << 2) + ((j & 7) >> 1);
    int qq = (hi ? 1 : 0) + ((j & 8) ? 2 : 0);
    hout[(size_t)((b >> 4) * 64 + (j >> 4)) * 256 + ldst * 8 + qq * 2 + (j & 1)] =
        __float2half(hv);
}

// ---- main persistent kernel: skewed L0/L1 pipeline, 1 sync per encoder phase ----
__global__ void __launch_bounds__(NTHR, 1)
rnn_main_kernel(const float* __restrict__ b0, const float* __restrict__ b1,
                const float* __restrict__ bf, float* __restrict__ out)
{
    const int ct   = blockIdx.x;
    const int tid  = threadIdx.x;
    const int w    = tid >> 5;
    const int lane = tid & 31;
    const int m    = w & 3;
    const int kseg = w >> 2;

    float c0r = 0.f, c1r = 0.f;

    const __half* Wb0 = g_W0f + (size_t)ct * 68 * 512;
    const __half* Wb1 = g_W1f + (size_t)ct * 128 * 512;

    __shared__ float red[6144];   // 24 KB

    // replay-safe local generation base (read once; all CTAs read before sync 1)
    unsigned gen = 0;
    if (tid == 0) gen = *(volatile unsigned*)&g_bar_gen;

    // h0(t) in g_H0F buffer (t&1); h1(t) in g_H1F (t&1).
    for (int p = 0; p <= 256; ++p) {
        if (p < 256) {
            const __half* a0    = g_XF + (size_t)(p * 4 + m) * 1024;
            const __half* h0old = g_H0F + (size_t)((((p - 1) & 1)) * 4 + m) * 16384;
            __half* h0out = g_H0F + (size_t)(p & 1) * 65536;
            cell_phase(Wb0, a0, 4, h0old, p ? 64 : 0, b0, c0r, h0out,
                       red, ct, kseg, m, lane);
        }
        if (p >= 1) {
            const int s1 = p - 1;
            const __half* h0new = g_H0F + (size_t)((s1 & 1) * 4 + m) * 16384;
            const __half* h1old = g_H1F + (size_t)((((s1 - 1) & 1)) * 4 + m) * 16384;
            __half* h1out = g_H1F + (size_t)(s1 & 1) * 65536;
            cell_phase(Wb1, h0new, 64, h1old, s1 ? 64 : 0, b1, c1r, h1out,
                       red, ct, kseg, m, lane);
        }
        grid_sync(gen); ++gen;
    }

    // Decoder: L0 | sync | L1 | sync | proj | sync
    for (int s = 256; s < 288; ++s) {
        const __half* a0 = (s == 256) ? g_XF + (size_t)(255 * 4 + m) * 1024
                                      : g_INPF + (size_t)m * 1024;
        cell_phase(Wb0, a0, 4,
                   g_H0F + (size_t)(((s - 1) & 1) * 4 + m) * 16384, 64, b0, c0r,
                   g_H0F + (size_t)(s & 1) * 65536, red, ct, kseg, m, lane);
        grid_sync(gen); ++gen;
        cell_phase(Wb1, g_H0F + (size_t)((s & 1) * 4 + m) * 16384, 64,
                   g_H1F + (size_t)(((s - 1) & 1) * 4 + m) * 16384, 64, b1, c1r,
                   g_H1F + (size_t)(s & 1) * 65536, red, ct, kseg, m, lane);
        grid_sync(gen); ++gen;

        float pacc[8];
        if (ct < 16 && w < 8) {
            const int mm = ct & 3, vg = ct >> 2;
            const __half* A  = g_H1F + (size_t)((s & 1) * 4 + mm) * 16384
                               + (size_t)(w * 8) * 256 + lane * 8;
            const __half* Wp = g_Wff + (size_t)(vg * 64 + w * 8) * 256 + lane * 8;
#pragma unroll
            for (int k = 0; k < 8; ++k) pacc[k] = 0.0f;
#pragma unroll
            for (int cc = 0; cc < 8; ++cc) {
                uint4 av = __ldcg((const uint4*)(A  + (size_t)cc * 256));
                uint4 wv = __ldg ((const uint4*)(Wp + (size_t)cc * 256));
                mma16816(pacc + 0, av, wv.x, wv.y);
                mma16816(pacc + 4, av, wv.z, wv.w);
            }
            if (w > 0) {
                float* dst = red + (size_t)(w - 1) * 256 + lane;
#pragma unroll
                for (int k = 0; k < 8; ++k) dst[k * 32] = pacc[k];
            }
        }
        __syncthreads();
        if (ct < 16 && w == 0) {
            float fsum[8];
#pragma unroll
            for (int k = 0; k < 8; ++k) fsum[k] = pacc[k];
#pragma unroll
            for (int ww = 1; ww < 8; ++ww) {
                const float* src = red + (size_t)(ww - 1) * 256 + lane;
#pragma unroll
                for (int k = 0; k < 8; ++k) fsum[k] += src[k * 32];
            }
            const int mm = ct & 3, vg = ct >> 2;
            const int tdec = s - TIN;
#pragma unroll
            for (int nt = 0; nt < 2; ++nt)
#pragma unroll
                for (int rr = 0; rr < 2; ++rr)
#pragma unroll
                    for (int e2 = 0; e2 < 2; ++e2) {
                        int b = mm * 16 + (lane >> 2) + rr * 8;
                        int v = vg * 16 + nt * 8 + ((lane & 3) << 1) + e2;
                        float val = fsum[nt * 4 + rr * 2 + e2] + __ldg(bf + v);
                        out[(size_t)(b * TOUT + tdec) * V_ + v] = val;
                        g_INPF[(size_t)((b >> 4) * 4 + (v >> 4)) * 256
                               + (((b & 7) << 2) + ((v & 7) >> 1)) * 8
                               + (rr + ((v & 8) ? 2 : 0)) * 2 + (v & 1)] =
                            __float2half(val);
                    }
        }
        grid_sync(gen); ++gen;
    }
}

extern "C" void kernel_launch(void* const* d_in, const int* in_sizes, int n_in,
                              void* d_out, int out_size) {
    const float* x  = (const float*)d_in[0];
    const float* W0 = (const float*)d_in[1];
    const float* b0 = (const float*)d_in[2];
    const float* W1 = (const float*)d_in[3];
    const float* b1 = (const float*)d_in[4];
    const float* Wf = (const float*)d_in[5];
    const float* bf = (const float*)d_in[6];
    float* out = (float*)d_out;

    prep_all<<<8192, 256>>>(x, W0, W1, Wf);
    rnn_main_kernel<<<NCTA, NTHR>>>(b0, b1, bf, out);
}

// round 15
// speedup vs baseline: 1.3172x; 1.1792x over previous
#include <cuda_runtime.h>
#include <cuda_fp16.h>
#include <math.h>

#define B_    64
#define TIN   256
#define V_    64
#define H_    1024
#define TOUT  32
#define NCTA  128
#define NTHR  512   // 16 warps: m = w&3 (batch tile), kseg = w>>2 (K quarter = epilogue nt)

__device__ __align__(16) __half g_W0f[4456448];
__device__ __align__(16) __half g_W1f[8388608];
__device__ __align__(16) __half g_Wff[65536];
__device__ __align__(16) __half g_XF [1048576];
__device__ __align__(16) __half g_H0F[131072];
__device__ __align__(16) __half g_H1F[131072];
__device__ __align__(16) __half g_INPF[4096];

__device__ unsigned g_bar_count = 0;
__device__ unsigned g_bar_gen   = 0;

__device__ __forceinline__ void mma16816(float* d, const uint4& a,
                                         unsigned b0, unsigned b1) {
    asm volatile(
        "mma.sync.aligned.m16n8k16.row.col.f32.f16.f16.f32 "
        "{%0,%1,%2,%3}, {%4,%5,%6,%7}, {%8,%9}, {%0,%1,%2,%3};\n"
        : "+f"(d[0]), "+f"(d[1]), "+f"(d[2]), "+f"(d[3])
        : "r"(a.x), "r"(a.y), "r"(a.z), "r"(a.w), "r"(b0), "r"(b1));
}

// fast activations: MUFU-based (rel err ~1e-6, far below fp16 noise)
__device__ __forceinline__ float sigm(float x) {
    return __fdividef(1.0f, 1.0f + __expf(-x));
}
__device__ __forceinline__ float tanh_f(float x) {
    return __fdividef(2.0f, 1.0f + __expf(-2.0f * x)) - 1.0f;
}

// flat grid barrier, fence-free release/acquire chain; gen tracked locally
__device__ __forceinline__ void grid_sync(unsigned gen) {
    __syncthreads();
    if (threadIdx.x == 0) {
        unsigned t;
        asm volatile("atom.add.acq_rel.gpu.u32 %0, [%1], 1;"
                     : "=r"(t) : "l"(&g_bar_count) : "memory");
        if (t == gridDim.x - 1) {
            g_bar_count = 0;
            asm volatile("st.release.gpu.u32 [%0], %1;"
                         :: "l"(&g_bar_gen), "r"(gen + 1u) : "memory");
        } else {
            unsigned cur;
            do {
                asm volatile("ld.acquire.gpu.u32 %0, [%1];"
                             : "=r"(cur) : "l"(&g_bar_gen) : "memory");
            } while ((int)(cur - (gen + 1u)) < 0);
        }
    }
    __syncthreads();
}

// ---- single merged prep kernel (fragment-order layouts verified R2-R13) ----
#define PW0 4456448
#define PW1 (PW0 + 8388608)
#define PWF (PW1 + 65536)
#define PX  (PWF + 1048576)
__global__ void prep_all(const float* __restrict__ x,  const float* __restrict__ W0,
                         const float* __restrict__ W1, const float* __restrict__ Wf) {
    for (int f = blockIdx.x * blockDim.x + threadIdx.x; f < PX; f += gridDim.x * blockDim.x) {
        if (f < PW0) {
            const int K = 1088, nchunk = 68;
            int e = f & 1, q = (f >> 1) & 3, l = (f >> 3) & 31, ng = (f >> 8) & 1;
            int rest = f >> 9;
            int c = rest % nchunk, ct = rest / nchunk;
            int n = (ng << 4) + ((q >> 1) << 3) + (l >> 2);
            int k = (c << 4) + ((q & 1) << 3) + ((l & 3) << 1) + e;
            int j = (ct << 3) + (n >> 2);
            g_W0f[f] = __float2half(W0[(size_t)((n & 3) * 1024 + j) * K + k]);
        } else if (f < PW1) {
            int f2 = f - PW0;
            const int K = 2048;
            int e = f2 & 1, q = (f2 >> 1) & 3, l = (f2 >> 3) & 31, ng = (f2 >> 8) & 1;
            int rest = f2 >> 9;
            int c = rest & 127, ct = rest >> 7;
            int n = (ng << 4) + ((q >> 1) << 3) + (l >> 2);
            int k = (c << 4) + ((q & 1) << 3) + ((l & 3) << 1) + e;
            int j = (ct << 3) + (n >> 2);
            g_W1f[f2] = __float2half(W1[(size_t)((n & 3) * 1024 + j) * K + k]);
        } else if (f < PWF) {
            int f3 = f - PW1;
            int e = f3 & 1, q = (f3 >> 1) & 3, l = (f3 >> 3) & 31;
            int rest = f3 >> 8;
            int c = rest & 63, vg = rest >> 6;
            int v = (vg << 4) + ((q >> 1) << 3) + (l >> 2);
            int j = (c << 4) + ((q & 1) << 3) + ((l & 3) << 1) + e;
            g_Wff[f3] = __float2half(Wf[(size_t)v * 1024 + j]);
        } else {
            int f4 = f - PWF;
            int e = f4 & 1, q = (f4 >> 1) & 3, l = (f4 >> 3) & 31;
            int rest = f4 >> 8;
            int c = rest & 3, m = (rest >> 2) & 3, t = rest >> 4;
            int b = (m << 4) + ((q & 1) << 3) + (l >> 2);
            int v = (c << 4) + ((q >> 1) << 3) + ((l & 3) << 1) + e;
            g_XF[f4] = __float2half(x[(size_t)(b * TIN + t) * V_ + v]);
        }
    }
}

// ---- GEMM over chunk range of concatenated A0|A1 ----
__device__ __forceinline__ void gemm_range(
    const __half* __restrict__ Wb,
    const __half* __restrict__ A0, int n0,
    const __half* __restrict__ A1,
    int start, int end, float acc[4][4], int lane)
{
    int e0 = min(end, n0);
    {
        const __half* a  = A0 + (size_t)start * 256 + lane * 8;
        const __half* wl = Wb + (size_t)start * 512 + lane * 8;
#pragma unroll 8
        for (int c = start; c < e0; ++c) {
            uint4 av = __ldcg((const uint4*)a);
            uint4 w0 = __ldg((const uint4*)wl);
            uint4 w1 = __ldg((const uint4*)(wl + 256));
            mma16816(acc[0], av, w0.x, w0.y);
            mma16816(acc[1], av, w0.z, w0.w);
            mma16816(acc[2], av, w1.x, w1.y);
            mma16816(acc[3], av, w1.z, w1.w);
            a += 256; wl += 512;
        }
    }
    int s1 = max(start, n0);
    {
        const __half* a  = A1 + (size_t)(s1 - n0) * 256 + lane * 8;
        const __half* wl = Wb + (size_t)s1 * 512 + lane * 8;
#pragma unroll 8
        for (int c = s1; c < end; ++c) {
            uint4 av = __ldcg((const uint4*)a);
            uint4 w0 = __ldg((const uint4*)wl);
            uint4 w1 = __ldg((const uint4*)(wl + 256));
            mma16816(acc[0], av, w0.x, w0.y);
            mma16816(acc[1], av, w0.z, w0.w);
            mma16816(acc[2], av, w1.x, w1.y);
            mma16816(acc[3], av, w1.z, w1.w);
            a += 256; wl += 512;
        }
    }
}

// ---- one LSTM cell phase: K split x4 across kseg; symmetric smem reduce
//      (conflict-free [warp][elem][lane] layout); epilogue parallel across all
//      16 warps: warp (m,kseg) handles output set (m, nt=kseg). ----
__device__ __forceinline__ void cell_phase(
    const __half* __restrict__ Wb,
    const __half* __restrict__ A0, int n0,
    const __half* __restrict__ A1, int n1,
    const float*  __restrict__ bias,
    float& cr, __half* __restrict__ hout,
    float* __restrict__ red,
    int ct, int kseg, int m, int lane)
{
    float acc[4][4];
#pragma unroll
    for (int i = 0; i < 4; ++i)
#pragma unroll
        for (int k = 0; k < 4; ++k) acc[i][k] = 0.0f;

    const int nc  = n0 + n1;
    const int len = nc >> 2;                    // nc in {4,68,128}
    gemm_range(Wb, A0, n0, A1, kseg * len, kseg * len + len, acc, lane);

    __syncthreads();   // guard smem region reuse (prev phase reads done)
    // STS: red[warp16][elem16][lane32], lane-major = conflict-free
    {
        float* dst = red + (size_t)(kseg * 4 + m) * 512 + lane;
#pragma unroll
        for (int i = 0; i < 4; ++i)
#pragma unroll
            for (int k = 0; k < 4; ++k) dst[(i * 4 + k) * 32] = acc[i][k];
    }
    __syncthreads();

    // epilogue: this warp owns nt = kseg for batch tile m
    const int nt = kseg;
    float d[4];
#pragma unroll
    for (int k = 0; k < 4; ++k) {
        float s = 0.0f;
#pragma unroll
        for (int ks = 0; ks < 4; ++ks)
            s += red[(size_t)(ks * 4 + m) * 512 + (nt * 4 + k) * 32 + lane];
        d[k] = s;
    }

    const bool hi = (lane & 1);
    int j  = ct * 8 + 2 * nt + ((lane & 3) >> 1);
    int g0 = (lane & 1) * 2;
    float bv0 = __ldg(bias + g0 * 1024 + j);
    float bv1 = __ldg(bias + (g0 + 1) * 1024 + j);
    float d0 = d[0] + bv0, d1 = d[1] + bv1, d2 = d[2] + bv0, d3 = d[3] + bv1;

    float sA = hi ? d0 : d2;
    float sB = hi ? d1 : d3;
    float rA = __shfl_xor_sync(0xffffffffu, sA, 1);
    float rB = __shfl_xor_sync(0xffffffffu, sB, 1);
    float gi = hi ? rA : d0;
    float gf = hi ? rB : d1;
    float gc = hi ? d2 : rA;
    float go = hi ? d3 : rB;

    float cn = sigm(gf) * cr + sigm(gi) * tanh_f(gc);
    cr = cn;
    float hv = sigm(go) * tanh_f(cn);

    int b = m * 16 + (lane >> 2) + (hi ? 8 : 0);
    int ldst = ((b & 7) << 2) + ((j & 7) >> 1);
    int qq = (hi ? 1 : 0) + ((j & 8) ? 2 : 0);
    hout[(size_t)((b >> 4) * 64 + (j >> 4)) * 256 + ldst * 8 + qq * 2 + (j & 1)] =
        __float2half(hv);
}

// ---- main persistent kernel: skewed L0/L1 pipeline, 1 sync per encoder phase ----
__global__ void __launch_bounds__(NTHR, 1)
rnn_main_kernel(const float* __restrict__ b0, const float* __restrict__ b1,
                const float* __restrict__ bf, float* __restrict__ out)
{
    const int ct   = blockIdx.x;
    const int tid  = threadIdx.x;
    const int w    = tid >> 5;
    const int lane = tid & 31;
    const int m    = w & 3;
    const int kseg = w >> 2;

    float c0r = 0.f, c1r = 0.f;

    const __half* Wb0 = g_W0f + (size_t)ct * 68 * 512;
    const __half* Wb1 = g_W1f + (size_t)ct * 128 * 512;

    __shared__ float red[8192];   // 32 KB: [warp][elem][lane] reduce / proj scratch

    // replay-safe local generation base (read before first sync)
    unsigned gen = 0;
    if (tid == 0) gen = *(volatile unsigned*)&g_bar_gen;

    // h0(t) in g_H0F buffer (t&1); h1(t) in g_H1F (t&1).
    for (int p = 0; p <= 256; ++p) {
        if (p < 256) {
            const __half* a0    = g_XF + (size_t)(p * 4 + m) * 1024;
            const __half* h0old = g_H0F + (size_t)((((p - 1) & 1)) * 4 + m) * 16384;
            __half* h0out = g_H0F + (size_t)(p & 1) * 65536;
            cell_phase(Wb0, a0, 4, h0old, p ? 64 : 0, b0, c0r, h0out,
                       red, ct, kseg, m, lane);
        }
        if (p >= 1) {
            const int s1 = p - 1;
            const __half* h0new = g_H0F + (size_t)((s1 & 1) * 4 + m) * 16384;
            const __half* h1old = g_H1F + (size_t)((((s1 - 1) & 1)) * 4 + m) * 16384;
            __half* h1out = g_H1F + (size_t)(s1 & 1) * 65536;
            cell_phase(Wb1, h0new, 64, h1old, s1 ? 64 : 0, b1, c1r, h1out,
                       red, ct, kseg, m, lane);
        }
        grid_sync(gen); ++gen;
    }

    // Decoder: L0 | sync | L1 | sync | proj | sync
    for (int s = 256; s < 288; ++s) {
        const __half* a0 = (s == 256) ? g_XF + (size_t)(255 * 4 + m) * 1024
                                      : g_INPF + (size_t)m * 1024;
        cell_phase(Wb0, a0, 4,
                   g_H0F + (size_t)(((s - 1) & 1) * 4 + m) * 16384, 64, b0, c0r,
                   g_H0F + (size_t)(s & 1) * 65536, red, ct, kseg, m, lane);
        grid_sync(gen); ++gen;
        cell_phase(Wb1, g_H0F + (size_t)((s & 1) * 4 + m) * 16384, 64,
                   g_H1F + (size_t)(((s - 1) & 1) * 4 + m) * 16384, 64, b1, c1r,
                   g_H1F + (size_t)(s & 1) * 65536, red, ct, kseg, m, lane);
        grid_sync(gen); ++gen;

        float pacc[8];
        if (ct < 16 && w < 8) {
            const int mm = ct & 3, vg = ct >> 2;
            const __half* A  = g_H1F + (size_t)((s & 1) * 4 + mm) * 16384
                               + (size_t)(w * 8) * 256 + lane * 8;
            const __half* Wp = g_Wff + (size_t)(vg * 64 + w * 8) * 256 + lane * 8;
#pragma unroll
            for (int k = 0; k < 8; ++k) pacc[k] = 0.0f;
#pragma unroll
            for (int cc = 0; cc < 8; ++cc) {
                uint4 av = __ldcg((const uint4*)(A  + (size_t)cc * 256));
                uint4 wv = __ldg ((const uint4*)(Wp + (size_t)cc * 256));
                mma16816(pacc + 0, av, wv.x, wv.y);
                mma16816(pacc + 4, av, wv.z, wv.w);
            }
            if (w > 0) {
                float* dst = red + (size_t)(w - 1) * 256 + lane;
#pragma unroll
                for (int k = 0; k < 8; ++k) dst[k * 32] = pacc[k];
            }
        }
        __syncthreads();
        if (ct < 16 && w == 0) {
            float fsum[8];
#pragma unroll
            for (int k = 0; k < 8; ++k) fsum[k] = pacc[k];
#pragma unroll
            for (int ww = 1; ww < 8; ++ww) {
                const float* src = red + (size_t)(ww - 1) * 256 + lane;
#pragma unroll
                for (int k = 0; k < 8; ++k) fsum[k] += src[k * 32];
            }
            const int mm = ct & 3, vg = ct >> 2;
            const int tdec = s - TIN;
#pragma unroll
            for (int nt = 0; nt < 2; ++nt)
#pragma unroll
                for (int rr = 0; rr < 2; ++rr)
#pragma unroll
                    for (int e2 = 0; e2 < 2; ++e2) {
                        int b = mm * 16 + (lane >> 2) + rr * 8;
                        int v = vg * 16 + nt * 8 + ((lane & 3) << 1) + e2;
                        float val = fsum[nt * 4 + rr * 2 + e2] + __ldg(bf + v);
                        out[(size_t)(b * TOUT + tdec) * V_ + v] = val;
                        g_INPF[(size_t)((b >> 4) * 4 + (v >> 4)) * 256
                               + (((b & 7) << 2) + ((v & 7) >> 1)) * 8
                               + (rr + ((v & 8) ? 2 : 0)) * 2 + (v & 1)] =
                            __float2half(val);
                    }
        }
        grid_sync(gen); ++gen;
    }
}

extern "C" void kernel_launch(void* const* d_in, const int* in_sizes, int n_in,
                              void* d_out, int out_size) {
    const float* x  = (const float*)d_in[0];
    const float* W0 = (const float*)d_in[1];
    const float* b0 = (const float*)d_in[2];
    const float* W1 = (const float*)d_in[3];
    const float* b1 = (const float*)d_in[4];
    const float* Wf = (const float*)d_in[5];
    const float* bf = (const float*)d_in[6];
    float* out = (float*)d_out;

    prep_all<<<8192, 256>>>(x, W0, W1, Wf);
    rnn_main_kernel<<<NCTA, NTHR>>>(b0, b1, bf, out);
}

// round 16
// speedup vs baseline: 1.4571x; 1.1062x over previous
#include <cuda_runtime.h>
#include <cuda_fp16.h>
#include <math.h>

#define B_    64
#define TIN   256
#define V_    64
#define H_    1024
#define TOUT  32
#define NCTA  128
#define NTHR  512   // 16 warps: mh = w&1 (m-tile pair), ksg = w>>1 (K eighth)
                    // epilogue ownership: m = w&3, nt = w>>2 (unchanged from R15)
#define RED_BYTES 65536

__device__ __align__(16) __half g_W0f[4456448];
__device__ __align__(16) __half g_W1f[8388608];
__device__ __align__(16) __half g_Wff[65536];
__device__ __align__(16) __half g_XF [1048576];
__device__ __align__(16) __half g_H0F[131072];
__device__ __align__(16) __half g_H1F[131072];
__device__ __align__(16) __half g_INPF[4096];

__device__ unsigned g_bar_count = 0;
__device__ unsigned g_bar_gen   = 0;

__device__ __forceinline__ void mma16816(float* d, const uint4& a,
                                         unsigned b0, unsigned b1) {
    asm volatile(
        "mma.sync.aligned.m16n8k16.row.col.f32.f16.f16.f32 "
        "{%0,%1,%2,%3}, {%4,%5,%6,%7}, {%8,%9}, {%0,%1,%2,%3};\n"
        : "+f"(d[0]), "+f"(d[1]), "+f"(d[2]), "+f"(d[3])
        : "r"(a.x), "r"(a.y), "r"(a.z), "r"(a.w), "r"(b0), "r"(b1));
}

__device__ __forceinline__ float sigm(float x) {
    return __fdividef(1.0f, 1.0f + __expf(-x));
}
__device__ __forceinline__ float tanh_f(float x) {
    return __fdividef(2.0f, 1.0f + __expf(-2.0f * x)) - 1.0f;
}

// flat grid barrier, fence-free release/acquire chain; gen tracked locally
__device__ __forceinline__ void grid_sync(unsigned gen) {
    __syncthreads();
    if (threadIdx.x == 0) {
        unsigned t;
        asm volatile("atom.add.acq_rel.gpu.u32 %0, [%1], 1;"
                     : "=r"(t) : "l"(&g_bar_count) : "memory");
        if (t == gridDim.x - 1) {
            g_bar_count = 0;
            asm volatile("st.release.gpu.u32 [%0], %1;"
                         :: "l"(&g_bar_gen), "r"(gen + 1u) : "memory");
        } else {
            unsigned cur;
            do {
                asm volatile("ld.acquire.gpu.u32 %0, [%1];"
                             : "=r"(cur) : "l"(&g_bar_gen) : "memory");
            } while ((int)(cur - (gen + 1u)) < 0);
        }
    }
    __syncthreads();
}

// ---- single merged prep kernel (fragment-order layouts verified R2-R15) ----
#define PW0 4456448
#define PW1 (PW0 + 8388608)
#define PWF (PW1 + 65536)
#define PX  (PWF + 1048576)
__global__ void prep_all(const float* __restrict__ x,  const float* __restrict__ W0,
                         const float* __restrict__ W1, const float* __restrict__ Wf) {
    for (int f = blockIdx.x * blockDim.x + threadIdx.x; f < PX; f += gridDim.x * blockDim.x) {
        if (f < PW0) {
            const int K = 1088, nchunk = 68;
            int e = f & 1, q = (f >> 1) & 3, l = (f >> 3) & 31, ng = (f >> 8) & 1;
            int rest = f >> 9;
            int c = rest % nchunk, ct = rest / nchunk;
            int n = (ng << 4) + ((q >> 1) << 3) + (l >> 2);
            int k = (c << 4) + ((q & 1) << 3) + ((l & 3) << 1) + e;
            int j = (ct << 3) + (n >> 2);
            g_W0f[f] = __float2half(W0[(size_t)((n & 3) * 1024 + j) * K + k]);
        } else if (f < PW1) {
            int f2 = f - PW0;
            const int K = 2048;
            int e = f2 & 1, q = (f2 >> 1) & 3, l = (f2 >> 3) & 31, ng = (f2 >> 8) & 1;
            int rest = f2 >> 9;
            int c = rest & 127, ct = rest >> 7;
            int n = (ng << 4) + ((q >> 1) << 3) + (l >> 2);
            int k = (c << 4) + ((q & 1) << 3) + ((l & 3) << 1) + e;
            int j = (ct << 3) + (n >> 2);
            g_W1f[f2] = __float2half(W1[(size_t)((n & 3) * 1024 + j) * K + k]);
        } else if (f < PWF) {
            int f3 = f - PW1;
            int e = f3 & 1, q = (f3 >> 1) & 3, l = (f3 >> 3) & 31;
            int rest = f3 >> 8;
            int c = rest & 63, vg = rest >> 6;
            int v = (vg << 4) + ((q >> 1) << 3) + (l >> 2);
            int j = (c << 4) + ((q & 1) << 3) + ((l & 3) << 1) + e;
            g_Wff[f3] = __float2half(Wf[(size_t)v * 1024 + j]);
        } else {
            int f4 = f - PWF;
            int e = f4 & 1, q = (f4 >> 1) & 3, l = (f4 >> 3) & 31;
            int rest = f4 >> 8;
            int c = rest & 3, m = (rest >> 2) & 3, t = rest >> 4;
            int b = (m << 4) + ((q & 1) << 3) + (l >> 2);
            int v = (c << 4) + ((q >> 1) << 3) + ((l & 3) << 1) + e;
            g_XF[f4] = __float2half(x[(size_t)(b * TIN + t) * V_ + v]);
        }
    }
}

// ---- GEMM over chunk range of concatenated A0|A1, TWO m-tiles per warp ----
// A0/A1 are bases of m-tile (mh*2); the second tile is at +mstride halfs.
__device__ __forceinline__ void gemm_range2(
    const __half* __restrict__ Wb,
    const __half* __restrict__ A0, int ms0, int n0,
    const __half* __restrict__ A1, int ms1,
    int start, int end, float acc[2][4][4], int lane)
{
    int e0 = min(end, n0);
    {
        const __half* a  = A0 + (size_t)start * 256 + lane * 8;
        const __half* wl = Wb + (size_t)start * 512 + lane * 8;
#pragma unroll 2
        for (int c = start; c < e0; ++c) {
            uint4 av0 = __ldcg((const uint4*)a);
            uint4 av1 = __ldcg((const uint4*)(a + ms0));
            uint4 w0 = __ldg((const uint4*)wl);
            uint4 w1 = __ldg((const uint4*)(wl + 256));
            mma16816(acc[0][0], av0, w0.x, w0.y);
            mma16816(acc[0][1], av0, w0.z, w0.w);
            mma16816(acc[0][2], av0, w1.x, w1.y);
            mma16816(acc[0][3], av0, w1.z, w1.w);
            mma16816(acc[1][0], av1, w0.x, w0.y);
            mma16816(acc[1][1], av1, w0.z, w0.w);
            mma16816(acc[1][2], av1, w1.x, w1.y);
            mma16816(acc[1][3], av1, w1.z, w1.w);
            a += 256; wl += 512;
        }
    }
    int s1 = max(start, n0);
    {
        const __half* a  = A1 + (size_t)(s1 - n0) * 256 + lane * 8;
        const __half* wl = Wb + (size_t)s1 * 512 + lane * 8;
#pragma unroll 2
        for (int c = s1; c < end; ++c) {
            uint4 av0 = __ldcg((const uint4*)a);
            uint4 av1 = __ldcg((const uint4*)(a + ms1));
            uint4 w0 = __ldg((const uint4*)wl);
            uint4 w1 = __ldg((const uint4*)(wl + 256));
            mma16816(acc[0][0], av0, w0.x, w0.y);
            mma16816(acc[0][1], av0, w0.z, w0.w);
            mma16816(acc[0][2], av0, w1.x, w1.y);
            mma16816(acc[0][3], av0, w1.z, w1.w);
            mma16816(acc[1][0], av1, w0.x, w0.y);
            mma16816(acc[1][1], av1, w0.z, w0.w);
            mma16816(acc[1][2], av1, w1.x, w1.y);
            mma16816(acc[1][3], av1, w1.z, w1.w);
            a += 256; wl += 512;
        }
    }
}

// ---- one LSTM cell phase: m2 x k8 partition; float4 smem reduce (64KB);
//      epilogue parallel: warp w owns output set (m = w&3, nt = w>>2). ----
__device__ __forceinline__ void cell_phase(
    const __half* __restrict__ Wb,
    const __half* __restrict__ A0b, int ms0, int n0,
    const __half* __restrict__ A1b, int ms1, int n1,
    const float*  __restrict__ bias,
    float& cr, __half* __restrict__ hout,
    float* __restrict__ red,
    int ct, int w, int lane)
{
    const int mh  = w & 1;        // m-tile pair: tiles (mh*2, mh*2+1)
    const int ksg = w >> 1;       // K eighth

    float acc[2][4][4];
#pragma unroll
    for (int mt = 0; mt < 2; ++mt)
#pragma unroll
        for (int i = 0; i < 4; ++i)
#pragma unroll
            for (int k = 0; k < 4; ++k) acc[mt][i][k] = 0.0f;

    const int nc    = n0 + n1;
    const int start = (ksg * nc) >> 3;
    const int end   = ((ksg + 1) * nc) >> 3;
    gemm_range2(Wb, A0b, ms0, n0, A1b, ms1, start, end, acc, lane);

    __syncthreads();   // prev-phase epilogue reads of red complete
    // STS: float4 slot index ((w*2+mt)*4+nt)*32 + lane  — conflict-free
    {
        float4* dst = (float4*)red + ((size_t)w * 2) * 4 * 32 + lane;
#pragma unroll
        for (int mt = 0; mt < 2; ++mt)
#pragma unroll
            for (int i = 0; i < 4; ++i)
                dst[(mt * 4 + i) * 32] =
                    make_float4(acc[mt][i][0], acc[mt][i][1], acc[mt][i][2], acc[mt][i][3]);
    }
    __syncthreads();

    // epilogue: warp w owns (m = w&3, nt = w>>2)
    const int m  = w & 3;
    const int nt = w >> 2;
    float4 s = make_float4(0.f, 0.f, 0.f, 0.f);
#pragma unroll
    for (int ks = 0; ks < 8; ++ks) {
        const int srcw = ks * 2 + (m >> 1);
        float4 v = ((const float4*)red)[(((size_t)srcw * 2 + (m & 1)) * 4 + nt) * 32 + lane];
        s.x += v.x; s.y += v.y; s.z += v.z; s.w += v.w;
    }

    const bool hi = (lane & 1);
    int j  = ct * 8 + 2 * nt + ((lane & 3) >> 1);
    int g0 = (lane & 1) * 2;
    float bv0 = __ldg(bias + g0 * 1024 + j);
    float bv1 = __ldg(bias + (g0 + 1) * 1024 + j);
    float d0 = s.x + bv0, d1 = s.y + bv1, d2 = s.z + bv0, d3 = s.w + bv1;

    float sA = hi ? d0 : d2;
    float sB = hi ? d1 : d3;
    float rA = __shfl_xor_sync(0xffffffffu, sA, 1);
    float rB = __shfl_xor_sync(0xffffffffu, sB, 1);
    float gi = hi ? rA : d0;
    float gf = hi ? rB : d1;
    float gc = hi ? d2 : rA;
    float go = hi ? d3 : rB;

    float cn = sigm(gf) * cr + sigm(gi) * tanh_f(gc);
    cr = cn;
    float hv = sigm(go) * tanh_f(cn);

    int b = m * 16 + (lane >> 2) + (hi ? 8 : 0);
    int ldst = ((b & 7) << 2) + ((j & 7) >> 1);
    int qq = (hi ? 1 : 0) + ((j & 8) ? 2 : 0);
    hout[(size_t)((b >> 4) * 64 + (j >> 4)) * 256 + ldst * 8 + qq * 2 + (j & 1)] =
        __float2half(hv);
}

// ---- main persistent kernel: skewed L0/L1 pipeline, 1 sync per encoder phase ----
__global__ void __launch_bounds__(NTHR, 1)
rnn_main_kernel(const float* __restrict__ b0, const float* __restrict__ b1,
                const float* __restrict__ bf, float* __restrict__ out)
{
    extern __shared__ float red[];   // 64 KB dynamic

    const int ct   = blockIdx.x;
    const int tid  = threadIdx.x;
    const int w    = tid >> 5;
    const int lane = tid & 31;
    const int mh   = w & 1;          // A-base m-tile pair for GEMM

    float c0r = 0.f, c1r = 0.f;

    const __half* Wb0 = g_W0f + (size_t)ct * 68 * 512;
    const __half* Wb1 = g_W1f + (size_t)ct * 128 * 512;

    unsigned gen = 0;
    if (tid == 0) gen = *(volatile unsigned*)&g_bar_gen;

    // h0(t) in g_H0F buffer (t&1); h1(t) in g_H1F (t&1).
    for (int p = 0; p <= 256; ++p) {
        if (p < 256) {
            const __half* a0    = g_XF + (size_t)(p * 4 + mh * 2) * 1024;
            const __half* h0old = g_H0F + (size_t)((((p - 1) & 1)) * 4 + mh * 2) * 16384;
            __half* h0out = g_H0F + (size_t)(p & 1) * 65536;
            cell_phase(Wb0, a0, 1024, 4, h0old, 16384, p ? 64 : 0, b0, c0r, h0out,
                       red, ct, w, lane);
        }
        if (p >= 1) {
            const int s1 = p - 1;
            const __half* h0new = g_H0F + (size_t)((s1 & 1) * 4 + mh * 2) * 16384;
            const __half* h1old = g_H1F + (size_t)((((s1 - 1) & 1)) * 4 + mh * 2) * 16384;
            __half* h1out = g_H1F + (size_t)(s1 & 1) * 65536;
            cell_phase(Wb1, h0new, 16384, 64, h1old, 16384, s1 ? 64 : 0, b1, c1r, h1out,
                       red, ct, w, lane);
        }
        grid_sync(gen); ++gen;
    }

    // Decoder: L0 | sync | L1 | sync | proj | sync
    for (int s = 256; s < 288; ++s) {
        const __half* a0 = (s == 256) ? g_XF + (size_t)(255 * 4 + mh * 2) * 1024
                                      : g_INPF + (size_t)(mh * 2) * 1024;
        cell_phase(Wb0, a0, 1024, 4,
                   g_H0F + (size_t)(((s - 1) & 1) * 4 + mh * 2) * 16384, 16384, 64,
                   b0, c0r, g_H0F + (size_t)(s & 1) * 65536, red, ct, w, lane);
        grid_sync(gen); ++gen;
        cell_phase(Wb1, g_H0F + (size_t)((s & 1) * 4 + mh * 2) * 16384, 16384, 64,
                   g_H1F + (size_t)(((s - 1) & 1) * 4 + mh * 2) * 16384, 16384, 64,
                   b1, c1r, g_H1F + (size_t)(s & 1) * 65536, red, ct, w, lane);
        grid_sync(gen); ++gen;

        float pacc[8];
        if (ct < 16 && w < 8) {
            const int mm = ct & 3, vg = ct >> 2;
            const __half* A  = g_H1F + (size_t)((s & 1) * 4 + mm) * 16384
                               + (size_t)(w * 8) * 256 + lane * 8;
            const __half* Wp = g_Wff + (size_t)(vg * 64 + w * 8) * 256 + lane * 8;
#pragma unroll
            for (int k = 0; k < 8; ++k) pacc[k] = 0.0f;
#pragma unroll
            for (int cc = 0; cc < 8; ++cc) {
                uint4 av = __ldcg((const uint4*)(A  + (size_t)cc * 256));
                uint4 wv = __ldg ((const uint4*)(Wp + (size_t)cc * 256));
                mma16816(pacc + 0, av, wv.x, wv.y);
                mma16816(pacc + 4, av, wv.z, wv.w);
            }
            if (w > 0) {
                float* dst = red + (size_t)(w - 1) * 256 + lane;
#pragma unroll
                for (int k = 0; k < 8; ++k) dst[k * 32] = pacc[k];
            }
        }
        __syncthreads();
        if (ct < 16 && w == 0) {
            float fsum[8];
#pragma unroll
            for (int k = 0; k < 8; ++k) fsum[k] = pacc[k];
#pragma unroll
            for (int ww = 1; ww < 8; ++ww) {
                const float* src = red + (size_t)(ww - 1) * 256 + lane;
#pragma unroll
                for (int k = 0; k < 8; ++k) fsum[k] += src[k * 32];
            }
            const int mm = ct & 3, vg = ct >> 2;
            const int tdec = s - TIN;
#pragma unroll
            for (int nt = 0; nt < 2; ++nt)
#pragma unroll
                for (int rr = 0; rr < 2; ++rr)
#pragma unroll
                    for (int e2 = 0; e2 < 2; ++e2) {
                        int b = mm * 16 + (lane >> 2) + rr * 8;
                        int v = vg * 16 + nt * 8 + ((lane & 3) << 1) + e2;
                        float val = fsum[nt * 4 + rr * 2 + e2] + __ldg(bf + v);
                        out[(size_t)(b * TOUT + tdec) * V_ + v] = val;
                        g_INPF[(size_t)((b >> 4) * 4 + (v >> 4)) * 256
                               + (((b & 7) << 2) + ((v & 7) >> 1)) * 8
                               + (rr + ((v & 8) ? 2 : 0)) * 2 + (v & 1)] =
                            __float2half(val);
                    }
        }
        grid_sync(gen); ++gen;
    }
}

extern "C" void kernel_launch(void* const* d_in, const int* in_sizes, int n_in,
                              void* d_out, int out_size) {
    const float* x  = (const float*)d_in[0];
    const float* W0 = (const float*)d_in[1];
    const float* b0 = (const float*)d_in[2];
    const float* W1 = (const float*)d_in[3];
    const float* b1 = (const float*)d_in[4];
    const float* Wf = (const float*)d_in[5];
    const float* bf = (const float*)d_in[6];
    float* out = (float*)d_out;

    prep_all<<<8192, 256>>>(x, W0, W1, Wf);
    cudaFuncSetAttribute(rnn_main_kernel,
                         cudaFuncAttributeMaxDynamicSharedMemorySize, RED_BYTES);
    rnn_main_kernel<<<NCTA, NTHR, RED_BYTES>>>(b0, b1, bf, out);
}